// round 4
// baseline (speedup 1.0000x reference)
#include <cuda_runtime.h>

#define DM    64
#define NPTS  1323
#define NTHR  256
#define SPB   256        // slots per block; 1 slot = 4 points = 3 float4

// one point through the inverse-Cholesky transform + gaussian
__device__ __forceinline__ float mvn_pt(float d0, float d1, float d2,
                                        float4 qa, float4 qb, float4 qc)
{
    d0 -= qa.x;
    d1 -= qa.y;
    d2 -= qa.z;
    float z0 = d0 * qa.w;
    float z1 = (d1 - qb.x * z0) * qb.y;
    float z2 = fmaf(-qb.w, z1, fmaf(-qb.z, z0, d2)) * qc.x;
    float maha = fmaf(z0, z0, fmaf(z1, z1, z2 * z2));
    return qc.y * __expf(-0.5f * maha);
}

__global__ __launch_bounds__(NTHR) void mvn_fused_kernel(
    const float* __restrict__ rep,
    const float* __restrict__ dxyz,
    const float* __restrict__ Wm,
    const float* __restrict__ bm,
    const float* __restrict__ Ws,
    const float* __restrict__ bs,
    float* __restrict__ out,
    int nrows)
{
    __shared__ float4 sd[SPB * 3];     // staged dxyz: 768 float4 = 12 KB
    __shared__ float4 sq[2][3];        // params for the <=2 rows this block touches

    const int t = threadIdx.x;
    const unsigned sbase = blockIdx.x * SPB;
    const unsigned p_first = 4u * sbase;
    // exact p/1323 for p < ~2e9 (magic: ceil(2^40/1323) = 831074549)
    const unsigned r_first = (unsigned)(((unsigned long long)p_first * 831074549ull) >> 40);

    // ---- stage 12 KB of dxyz, fully coalesced (4 lines per LDG.128) ----
    const float4* __restrict__ dp4 = (const float4*)dxyz + 3u * (size_t)sbase;
    #pragma unroll
    for (int k = 0; k < 3; k++)
        sd[t + k * NTHR] = __ldcs(dp4 + t + k * NTHR);

    // ---- warps 0,1: compute params for rows r_first, r_first+1 (overlaps staging) ----
    const int wid = t >> 5, lane = t & 31;
    if (wid < 2) {
        int r = (int)r_first + wid;
        if (r > nrows - 1) r = nrows - 1;
        const float2 v = ((const float2*)(rep + (size_t)r * DM))[lane];

        float dots[9];
        #pragma unroll
        for (int c = 0; c < 9; c++) {
            const float* w = (c < 3) ? (Wm + c * DM) : (Ws + (c - 3) * DM);
            const float2 wv = ((const float2*)w)[lane];
            float partial = fmaf(v.x, wv.x, v.y * wv.y);
            #pragma unroll
            for (int off = 16; off > 0; off >>= 1)
                partial += __shfl_xor_sync(0xFFFFFFFFu, partial, off);
            dots[c] = partial;   // full sum on every lane
        }

        if (lane == 0) {
            float m0 = dots[0] + bm[0];
            float m1 = dots[1] + bm[1];
            float m2 = dots[2] + bm[2];
            float s[6];
            #pragma unroll
            for (int i = 0; i < 6; i++)
                s[i] = 1.0f / (1.0f + __expf(-(dots[3 + i] + bs[i])));   // sigmoid
            // softplus(x) for x in (0,1): safe as log(1+exp(x))
            float L00 = __logf(1.0f + __expf(s[0]));
            float L10 = s[1];
            float L11 = __logf(1.0f + __expf(s[2]));
            float L20 = s[3];
            float L21 = s[4];
            float L22 = __logf(1.0f + __expf(s[5]));
            const float TWO_PI_1P5 = 15.749609945722419f;   // (2*pi)^1.5
            float C = 1.0f / (L00 * L11 * L22 * TWO_PI_1P5);
            sq[wid][0] = make_float4(m0, m1, m2, 1.0f / L00);
            sq[wid][1] = make_float4(L10, 1.0f / L11, L20, L21);
            sq[wid][2] = make_float4(1.0f / L22, C, 0.0f, 0.0f);
        }
    }
    __syncthreads();

    // ---- compute: one slot per thread, conflict-free LDS.128 (48B lane stride) ----
    const float4 a = sd[3 * t + 0];
    const float4 b = sd[3 * t + 1];
    const float4 c = sd[3 * t + 2];
    // points: p0=(a.x,a.y,a.z) p1=(a.w,b.x,b.y) p2=(b.z,b.w,c.x) p3=(c.y,c.z,c.w)

    const unsigned p0 = p_first + 4u * t;
    const unsigned r0 = (unsigned)(((unsigned long long)p0 * 831074549ull) >> 40);
    const unsigned r3 = (unsigned)(((unsigned long long)(p0 + 3u) * 831074549ull) >> 40);
    const int i0 = (int)(r0 - r_first);     // 0 or 1

    const float4 qa = sq[i0][0], qb = sq[i0][1], qc = sq[i0][2];

    float4 res;
    if (r0 == r3) {
        // fast path (99.7%)
        res.x = mvn_pt(a.x, a.y, a.z, qa, qb, qc);
        res.y = mvn_pt(a.w, b.x, b.y, qa, qb, qc);
        res.z = mvn_pt(b.z, b.w, c.x, qa, qb, qc);
        res.w = mvn_pt(c.y, c.z, c.w, qa, qb, qc);
    } else {
        // slot crosses the row boundary: points >= E use the second row's params
        const unsigned E = (r0 + 1u) * (unsigned)NPTS;
        const float4 qa2 = sq[1][0], qb2 = sq[1][1], qc2 = sq[1][2];
        res.x = (p0 + 0 < E) ? mvn_pt(a.x, a.y, a.z, qa, qb, qc)
                             : mvn_pt(a.x, a.y, a.z, qa2, qb2, qc2);
        res.y = (p0 + 1 < E) ? mvn_pt(a.w, b.x, b.y, qa, qb, qc)
                             : mvn_pt(a.w, b.x, b.y, qa2, qb2, qc2);
        res.z = (p0 + 2 < E) ? mvn_pt(b.z, b.w, c.x, qa, qb, qc)
                             : mvn_pt(b.z, b.w, c.x, qa2, qb2, qc2);
        res.w = (p0 + 3 < E) ? mvn_pt(c.y, c.z, c.w, qa, qb, qc)
                             : mvn_pt(c.y, c.z, c.w, qa2, qb2, qc2);
    }

    __stcs((float4*)out + sbase + t, res);
}

extern "C" void kernel_launch(void* const* d_in, const int* in_sizes, int n_in,
                              void* d_out, int out_size)
{
    const float* rep  = (const float*)d_in[0];
    const float* dxyz = (const float*)d_in[1];
    const float* Wm   = (const float*)d_in[2];
    const float* bm   = (const float*)d_in[3];
    const float* Ws   = (const float*)d_in[4];
    const float* bs   = (const float*)d_in[5];
    // d_in[6] = num_planes (fixed 3) — unused

    float* out = (float*)d_out;

    const int nrows = in_sizes[0] / DM;                       // 16384
    const unsigned total_slots = (unsigned)nrows * NPTS / 4u; // 5419008
    const unsigned blocks = total_slots / SPB;                // 21168, exact
    mvn_fused_kernel<<<blocks, NTHR>>>(rep, dxyz, Wm, bm, Ws, bs, out, nrows);
}

// round 5
// speedup vs baseline: 1.4409x; 1.4409x over previous
#include <cuda_runtime.h>

#define DM        64
#define NPTS      1323
#define MAXROWS   16384
#define NTHR      256

// param records: 12 floats per row (3 float4): m0,m1,m2,iL00 | L10,iL11,L20,L21 | iL22,C,pad,pad
__device__ float g_params[MAXROWS * 12];

// ---------------- Kernel A: per-row parameters (one warp per row) ----------------
__global__ __launch_bounds__(NTHR) void mvn_params_kernel(
    const float* __restrict__ rep,
    const float* __restrict__ Wm,
    const float* __restrict__ bm,
    const float* __restrict__ Ws,
    const float* __restrict__ bs,
    int nrows)
{
    const int warp = (blockIdx.x * NTHR + threadIdx.x) >> 5;
    const int lane = threadIdx.x & 31;
    if (warp >= nrows) return;

    const float2 v = ((const float2*)(rep + (size_t)warp * DM))[lane];

    float dots[9];
    #pragma unroll
    for (int c = 0; c < 9; c++) {
        const float* w = (c < 3) ? (Wm + c * DM) : (Ws + (c - 3) * DM);
        const float2 wv = ((const float2*)w)[lane];
        float partial = fmaf(v.x, wv.x, v.y * wv.y);
        #pragma unroll
        for (int off = 16; off > 0; off >>= 1)
            partial += __shfl_xor_sync(0xFFFFFFFFu, partial, off);
        dots[c] = partial;      // full sum on every lane
    }

    // lanes 0..5 compute the 6 sigmoids (+softplus) in parallel
    float sig = 0.0f, splus = 0.0f;
    if (lane < 6) {
        sig = 1.0f / (1.0f + __expf(-(dots[3 + lane] + bs[lane])));
        splus = __logf(1.0f + __expf(sig));     // sig in (0,1): always safe
    }
    const float L00 = __shfl_sync(0xFFFFFFFFu, splus, 0);
    const float L10 = __shfl_sync(0xFFFFFFFFu, sig,   1);
    const float L11 = __shfl_sync(0xFFFFFFFFu, splus, 2);
    const float L20 = __shfl_sync(0xFFFFFFFFu, sig,   3);
    const float L21 = __shfl_sync(0xFFFFFFFFu, sig,   4);
    const float L22 = __shfl_sync(0xFFFFFFFFu, splus, 5);

    if (lane == 0) {
        const float TWO_PI_1P5 = 15.749609945722419f;   // (2*pi)^1.5
        float C = 1.0f / (L00 * L11 * L22 * TWO_PI_1P5);
        float4* q = (float4*)(g_params + warp * 12);
        q[0] = make_float4(dots[0] + bm[0], dots[1] + bm[1], dots[2] + bm[2], 1.0f / L00);
        q[1] = make_float4(L10, 1.0f / L11, L20, L21);
        q[2] = make_float4(1.0f / L22, C, 0.0f, 0.0f);
    }
}

// one point through the inverse-Cholesky transform + gaussian
__device__ __forceinline__ float mvn_pt(float d0, float d1, float d2,
                                        float4 qa, float4 qb, float4 qc)
{
    d0 -= qa.x;
    d1 -= qa.y;
    d2 -= qa.z;
    float z0 = d0 * qa.w;
    float z1 = (d1 - qb.x * z0) * qb.y;
    float z2 = fmaf(-qb.w, z1, fmaf(-qb.z, z0, d2)) * qc.x;
    float maha = fmaf(z0, z0, fmaf(z1, z1, z2 * z2));
    return qc.y * __expf(-0.5f * maha);
}

// ---------------- Kernel B: pure streaming, one slot (4 points) per thread ----------------
__global__ __launch_bounds__(NTHR) void mvn_stream_kernel(
    const float* __restrict__ dxyz,
    float* __restrict__ out)
{
    const unsigned s = blockIdx.x * NTHR + threadIdx.x;   // slot index, grid sized exactly
    const unsigned p0 = 4u * s;

    // exact p/1323 for p < ~2e9 (magic: ceil(2^40/1323) = 831074549, err 551)
    const unsigned r0 = (unsigned)(((unsigned long long)p0 * 831074549ull) >> 40);
    const unsigned r3 = (unsigned)(((unsigned long long)(p0 + 3u) * 831074549ull) >> 40);

    // issue the A-independent streaming loads BEFORE the grid-dependency sync
    const float4* __restrict__ dp4 = (const float4*)dxyz + 3u * (size_t)s;
    const float4 a = __ldcs(dp4 + 0);
    const float4 b = __ldcs(dp4 + 1);
    const float4 c = __ldcs(dp4 + 2);
    // points: p0=(a.x,a.y,a.z) p1=(a.w,b.x,b.y) p2=(b.z,b.w,c.x) p3=(c.y,c.z,c.w)

    // PDL: wait for kernel A's params (first wave only pays; later waves free)
    cudaGridDependencySynchronize();

    const float4* __restrict__ P = (const float4*)g_params;
    float4 qa = __ldg(P + 3u * r0 + 0);
    float4 qb = __ldg(P + 3u * r0 + 1);
    float4 qc = __ldg(P + 3u * r0 + 2);

    float4 res;
    if (r0 == r3) {
        // fast path (99.7%)
        res.x = mvn_pt(a.x, a.y, a.z, qa, qb, qc);
        res.y = mvn_pt(a.w, b.x, b.y, qa, qb, qc);
        res.z = mvn_pt(b.z, b.w, c.x, qa, qb, qc);
        res.w = mvn_pt(c.y, c.z, c.w, qa, qb, qc);
    } else {
        // slot crosses a row boundary: points >= E use row r3's params
        const unsigned E = (r0 + 1u) * (unsigned)NPTS;
        const float4 qa2 = __ldg(P + 3u * r3 + 0);
        const float4 qb2 = __ldg(P + 3u * r3 + 1);
        const float4 qc2 = __ldg(P + 3u * r3 + 2);
        res.x = (p0 + 0 < E) ? mvn_pt(a.x, a.y, a.z, qa, qb, qc)
                             : mvn_pt(a.x, a.y, a.z, qa2, qb2, qc2);
        res.y = (p0 + 1 < E) ? mvn_pt(a.w, b.x, b.y, qa, qb, qc)
                             : mvn_pt(a.w, b.x, b.y, qa2, qb2, qc2);
        res.z = (p0 + 2 < E) ? mvn_pt(b.z, b.w, c.x, qa, qb, qc)
                             : mvn_pt(b.z, b.w, c.x, qa2, qb2, qc2);
        res.w = (p0 + 3 < E) ? mvn_pt(c.y, c.z, c.w, qa, qb, qc)
                             : mvn_pt(c.y, c.z, c.w, qa2, qb2, qc2);
    }

    __stcs((float4*)out + s, res);
}

extern "C" void kernel_launch(void* const* d_in, const int* in_sizes, int n_in,
                              void* d_out, int out_size)
{
    const float* rep  = (const float*)d_in[0];
    const float* dxyz = (const float*)d_in[1];
    const float* Wm   = (const float*)d_in[2];
    const float* bm   = (const float*)d_in[3];
    const float* Ws   = (const float*)d_in[4];
    const float* bs   = (const float*)d_in[5];
    // d_in[6] = num_planes (fixed 3) — unused

    float* out = (float*)d_out;

    int nrows = in_sizes[0] / DM;          // 16384
    if (nrows > MAXROWS) nrows = MAXROWS;

    // Kernel A: 8 rows per 256-thread block (plain launch)
    const int blkA = (nrows * 32 + NTHR - 1) / NTHR;
    mvn_params_kernel<<<blkA, NTHR>>>(rep, Wm, bm, Ws, bs, nrows);

    // Kernel B: PDL launch so it overlaps A; grid-dependency sync inside guards g_params
    const unsigned total_slots = (unsigned)nrows * NPTS / 4u;   // 5419008
    const unsigned blkB = (total_slots + NTHR - 1) / NTHR;      // 21168

    cudaLaunchConfig_t cfg = {};
    cfg.gridDim  = dim3(blkB, 1, 1);
    cfg.blockDim = dim3(NTHR, 1, 1);
    cfg.dynamicSmemBytes = 0;
    cudaLaunchAttribute attrs[1];
    attrs[0].id = cudaLaunchAttributeProgrammaticStreamSerialization;
    attrs[0].val.programmaticStreamSerializationAllowed = 1;
    cfg.attrs = attrs;
    cfg.numAttrs = 1;
    cudaLaunchKernelEx(&cfg, mvn_stream_kernel, dxyz, out);
}

// round 6
// speedup vs baseline: 1.4731x; 1.0224x over previous
#include <cuda_runtime.h>

#define DM        64
#define NPTS      1323
#define MAXROWS   16384
#define NTHR      256

// param records: 12 floats per row (3 float4): m0,m1,m2,iL00 | L10,iL11,L20,L21 | iL22,C,pad,pad
__device__ float g_params[MAXROWS * 12];

// ---------------- Kernel A: per-row parameters (one warp per row) ----------------
__global__ __launch_bounds__(NTHR) void mvn_params_kernel(
    const float* __restrict__ rep,
    const float* __restrict__ Wm,
    const float* __restrict__ bm,
    const float* __restrict__ Ws,
    const float* __restrict__ bs,
    int nrows)
{
    // release the dependent (stream) kernel immediately: its pre-sync section
    // is A-independent; cudaGridDependencySynchronize there still waits for
    // A's full completion before g_params is read.
    cudaTriggerProgrammaticLaunchCompletion();

    const int warp = (blockIdx.x * NTHR + threadIdx.x) >> 5;
    const int lane = threadIdx.x & 31;
    if (warp >= nrows) return;

    const float2 v = ((const float2*)(rep + (size_t)warp * DM))[lane];

    float dots[9];
    #pragma unroll
    for (int c = 0; c < 9; c++) {
        const float* w = (c < 3) ? (Wm + c * DM) : (Ws + (c - 3) * DM);
        const float2 wv = ((const float2*)w)[lane];
        float partial = fmaf(v.x, wv.x, v.y * wv.y);
        #pragma unroll
        for (int off = 16; off > 0; off >>= 1)
            partial += __shfl_xor_sync(0xFFFFFFFFu, partial, off);
        dots[c] = partial;      // full sum on every lane
    }

    // lanes 0..5 compute the 6 sigmoids (+softplus) in parallel
    float sig = 0.0f, splus = 0.0f;
    if (lane < 6) {
        sig = 1.0f / (1.0f + __expf(-(dots[3 + lane] + bs[lane])));
        splus = __logf(1.0f + __expf(sig));     // sig in (0,1): always safe
    }
    const float L00 = __shfl_sync(0xFFFFFFFFu, splus, 0);
    const float L10 = __shfl_sync(0xFFFFFFFFu, sig,   1);
    const float L11 = __shfl_sync(0xFFFFFFFFu, splus, 2);
    const float L20 = __shfl_sync(0xFFFFFFFFu, sig,   3);
    const float L21 = __shfl_sync(0xFFFFFFFFu, sig,   4);
    const float L22 = __shfl_sync(0xFFFFFFFFu, splus, 5);

    if (lane == 0) {
        const float TWO_PI_1P5 = 15.749609945722419f;   // (2*pi)^1.5
        float C = 1.0f / (L00 * L11 * L22 * TWO_PI_1P5);
        float4* q = (float4*)(g_params + warp * 12);
        q[0] = make_float4(dots[0] + bm[0], dots[1] + bm[1], dots[2] + bm[2], 1.0f / L00);
        q[1] = make_float4(L10, 1.0f / L11, L20, L21);
        q[2] = make_float4(1.0f / L22, C, 0.0f, 0.0f);
    }
}

// one point through the inverse-Cholesky transform + gaussian
__device__ __forceinline__ float mvn_pt(float d0, float d1, float d2,
                                        float4 qa, float4 qb, float4 qc)
{
    d0 -= qa.x;
    d1 -= qa.y;
    d2 -= qa.z;
    float z0 = d0 * qa.w;
    float z1 = (d1 - qb.x * z0) * qb.y;
    float z2 = fmaf(-qb.w, z1, fmaf(-qb.z, z0, d2)) * qc.x;
    float maha = fmaf(z0, z0, fmaf(z1, z1, z2 * z2));
    return qc.y * __expf(-0.5f * maha);
}

// process one slot (4 points packed in 3 float4) given its global slot index
__device__ __forceinline__ float4 mvn_slot(unsigned s, float4 a, float4 b, float4 c)
{
    const unsigned p0 = 4u * s;
    // exact p/1323 for p < ~2e9 (magic: ceil(2^40/1323) = 831074549)
    const unsigned r0 = (unsigned)(((unsigned long long)p0 * 831074549ull) >> 40);
    const unsigned r3 = (unsigned)(((unsigned long long)(p0 + 3u) * 831074549ull) >> 40);

    const float4* __restrict__ P = (const float4*)g_params;
    const float4 qa = __ldg(P + 3u * r0 + 0);
    const float4 qb = __ldg(P + 3u * r0 + 1);
    const float4 qc = __ldg(P + 3u * r0 + 2);

    float4 res;
    if (r0 == r3) {
        // fast path (99.7%)
        res.x = mvn_pt(a.x, a.y, a.z, qa, qb, qc);
        res.y = mvn_pt(a.w, b.x, b.y, qa, qb, qc);
        res.z = mvn_pt(b.z, b.w, c.x, qa, qb, qc);
        res.w = mvn_pt(c.y, c.z, c.w, qa, qb, qc);
    } else {
        // slot crosses a row boundary: points >= E use row r3's params
        const unsigned E = (r0 + 1u) * (unsigned)NPTS;
        const float4 qa2 = __ldg(P + 3u * r3 + 0);
        const float4 qb2 = __ldg(P + 3u * r3 + 1);
        const float4 qc2 = __ldg(P + 3u * r3 + 2);
        res.x = (p0 + 0 < E) ? mvn_pt(a.x, a.y, a.z, qa, qb, qc)
                             : mvn_pt(a.x, a.y, a.z, qa2, qb2, qc2);
        res.y = (p0 + 1 < E) ? mvn_pt(a.w, b.x, b.y, qa, qb, qc)
                             : mvn_pt(a.w, b.x, b.y, qa2, qb2, qc2);
        res.z = (p0 + 2 < E) ? mvn_pt(b.z, b.w, c.x, qa, qb, qc)
                             : mvn_pt(b.z, b.w, c.x, qa2, qb2, qc2);
        res.w = (p0 + 3 < E) ? mvn_pt(c.y, c.z, c.w, qa, qb, qc)
                             : mvn_pt(c.y, c.z, c.w, qa2, qb2, qc2);
    }
    return res;
}

// ---------------- Kernel B: pure streaming, TWO slots (8 points) per thread ----------------
__global__ __launch_bounds__(NTHR) void mvn_stream_kernel(
    const float* __restrict__ dxyz,
    float* __restrict__ out)
{
    const int t = threadIdx.x;
    const unsigned s0 = blockIdx.x * (2u * NTHR) + t;     // slot 0
    const unsigned s1 = s0 + NTHR;                        // slot 1 (coalesced pair)

    // issue all 6 A-independent streaming loads BEFORE the grid-dependency sync
    const float4* __restrict__ dpA = (const float4*)dxyz + 3u * (size_t)s0;
    const float4* __restrict__ dpB = (const float4*)dxyz + 3u * (size_t)s1;
    const float4 a0 = __ldcs(dpA + 0);
    const float4 b0 = __ldcs(dpA + 1);
    const float4 c0 = __ldcs(dpA + 2);
    const float4 a1 = __ldcs(dpB + 0);
    const float4 b1 = __ldcs(dpB + 1);
    const float4 c1 = __ldcs(dpB + 2);

    // PDL: wait for kernel A's params (first wave pays; later waves free)
    cudaGridDependencySynchronize();

    const float4 r0 = mvn_slot(s0, a0, b0, c0);
    const float4 r1 = mvn_slot(s1, a1, b1, c1);

    __stcs((float4*)out + s0, r0);
    __stcs((float4*)out + s1, r1);
}

extern "C" void kernel_launch(void* const* d_in, const int* in_sizes, int n_in,
                              void* d_out, int out_size)
{
    const float* rep  = (const float*)d_in[0];
    const float* dxyz = (const float*)d_in[1];
    const float* Wm   = (const float*)d_in[2];
    const float* bm   = (const float*)d_in[3];
    const float* Ws   = (const float*)d_in[4];
    const float* bs   = (const float*)d_in[5];
    // d_in[6] = num_planes (fixed 3) — unused

    float* out = (float*)d_out;

    int nrows = in_sizes[0] / DM;          // 16384
    if (nrows > MAXROWS) nrows = MAXROWS;

    // Kernel A: 8 rows per 256-thread block; triggers PDL completion at entry
    const int blkA = (nrows * 32 + NTHR - 1) / NTHR;
    mvn_params_kernel<<<blkA, NTHR>>>(rep, Wm, bm, Ws, bs, nrows);

    // Kernel B: PDL launch; 2 slots per thread; 5419008 slots / 512 = 10584 blocks exact
    const unsigned total_slots = (unsigned)nrows * NPTS / 4u;
    const unsigned blkB = total_slots / (2u * NTHR);

    cudaLaunchConfig_t cfg = {};
    cfg.gridDim  = dim3(blkB, 1, 1);
    cfg.blockDim = dim3(NTHR, 1, 1);
    cfg.dynamicSmemBytes = 0;
    cudaLaunchAttribute attrs[1];
    attrs[0].id = cudaLaunchAttributeProgrammaticStreamSerialization;
    attrs[0].val.programmaticStreamSerializationAllowed = 1;
    cfg.attrs = attrs;
    cfg.numAttrs = 1;
    cudaLaunchKernelEx(&cfg, mvn_stream_kernel, dxyz, out);
}